// round 1
// baseline (speedup 1.0000x reference)
#include <cuda_runtime.h>
#include <cuda_bf16.h>
#include <math.h>

#define N_TOK   4096
#define DM      1024
#define N_EXP   8
#define FFH     2048
#define ROWS_PAD 8704   // 8192 assigned rows + 8 experts * 63 padding, rounded

// ---------------- device scratch (no allocations allowed) ----------------
__device__ float g_hbuf[(size_t)ROWS_PAD * FFH];   // ~71 MB hidden activations
__device__ int   g_slot[ROWS_PAD];                 // compacted row -> token
__device__ float g_slotw[ROWS_PAD];                // compacted row -> combine weight
__device__ int   g_counts[N_EXP];
__device__ float g_probsum[N_EXP];
__device__ int   g_aoff[N_EXP + 1];                // 64-aligned expert offsets
__device__ int   g_cursor[N_EXP];
__device__ int   g_tok_e[N_TOK * 2];
__device__ float g_tok_w[N_TOK * 2];

// ---------------- init: zero output + counters ----------------
__global__ void init_kernel(float* __restrict__ out, int out_elems) {
    int i = blockIdx.x * blockDim.x + threadIdx.x;
    int stride = gridDim.x * blockDim.x;
    for (int j = i; j < out_elems; j += stride) out[j] = 0.0f;
    if (blockIdx.x == 0 && threadIdx.x < N_EXP) {
        g_counts[threadIdx.x]  = 0;
        g_probsum[threadIdx.x] = 0.0f;
    }
}

// ---------------- router: warp per token ----------------
__global__ void __launch_bounds__(256) router_kernel(const float* __restrict__ x,
                                                     const float* __restrict__ rw) {
    int warp = blockIdx.x * 8 + (threadIdx.x >> 5);
    int lane = threadIdx.x & 31;
    if (warp >= N_TOK) return;

    const float* xr = x + (size_t)warp * DM;
    float acc[N_EXP];
#pragma unroll
    for (int e = 0; e < N_EXP; e++) acc[e] = 0.0f;

    for (int j = lane; j < DM; j += 32) {
        float xv = xr[j];
#pragma unroll
        for (int e = 0; e < N_EXP; e++)
            acc[e] = fmaf(xv, rw[e * DM + j], acc[e]);
    }
#pragma unroll
    for (int e = 0; e < N_EXP; e++) {
#pragma unroll
        for (int o = 16; o > 0; o >>= 1)
            acc[e] += __shfl_xor_sync(0xFFFFFFFFu, acc[e], o);
    }

    if (lane == 0) {
        float m = acc[0];
#pragma unroll
        for (int e = 1; e < N_EXP; e++) m = fmaxf(m, acc[e]);
        float ex[N_EXP], s = 0.0f;
#pragma unroll
        for (int e = 0; e < N_EXP; e++) { ex[e] = expf(acc[e] - m); s += ex[e]; }
        float inv = 1.0f / s;

        // top-2 by logits (softmax monotone => same indices as probs);
        // ties broken toward lower index to match lax.top_k
        int i0 = 0;
#pragma unroll
        for (int e = 1; e < N_EXP; e++) if (acc[e] > acc[i0]) i0 = e;
        int i1 = -1;
#pragma unroll
        for (int e = 0; e < N_EXP; e++) {
            if (e == i0) continue;
            if (i1 < 0 || acc[e] > acc[i1]) i1 = e;
        }
        float p0 = ex[i0] * inv, p1 = ex[i1] * inv;
        float rcp = 1.0f / (p0 + p1);
        g_tok_e[2 * warp + 0] = i0; g_tok_w[2 * warp + 0] = p0 * rcp;
        g_tok_e[2 * warp + 1] = i1; g_tok_w[2 * warp + 1] = p1 * rcp;

        atomicAdd(&g_counts[i0], 1);
        atomicAdd(&g_counts[i1], 1);
#pragma unroll
        for (int e = 0; e < N_EXP; e++)
            atomicAdd(&g_probsum[e], ex[e] * inv);
    }
}

// ---------------- finalize: offsets + aux loss ----------------
__global__ void finalize_kernel(float* auxp) {
    if (threadIdx.x == 0 && blockIdx.x == 0) {
        int off = 0;
        float s = 0.0f;
        for (int e = 0; e < N_EXP; e++) {
            g_aoff[e] = off;
            off += (g_counts[e] + 63) & ~63;
            g_cursor[e] = 0;
            float f_i = (float)g_counts[e] / (float)(N_TOK * 2);
            float P_i = g_probsum[e] / (float)N_TOK;
            s += f_i * P_i;
        }
        g_aoff[N_EXP] = off;
        if (auxp) *auxp = (float)N_EXP * s;
    }
}

// ---------------- scatter: compact tokens by expert ----------------
__global__ void scatter_kernel() {
    int t = blockIdx.x * blockDim.x + threadIdx.x;
    if (t >= N_TOK) return;
#pragma unroll
    for (int k = 0; k < 2; k++) {
        int e = g_tok_e[2 * t + k];
        int p = atomicAdd(&g_cursor[e], 1);
        int idx = g_aoff[e] + p;
        g_slot[idx]  = t;
        g_slotw[idx] = g_tok_w[2 * t + k];
    }
}

// ---------------- GEMM1: h = silu(x_gather @ w1[e]^T + b1[e]) ----------------
// 64x64 tile, 256 threads, 4x4 micro-tile, K-step 16
__global__ void __launch_bounds__(256) gemm1_kernel(const float* __restrict__ x,
                                                    const float* __restrict__ w1,
                                                    const float* __restrict__ b1) {
    const int e   = blockIdx.z;
    const int cnt = g_counts[e];
    const int rt  = blockIdx.x;
    if (rt * 64 >= cnt) return;
    const int base = g_aoff[e];
    const int ct   = blockIdx.y;

    __shared__ float As[64][17];
    __shared__ float Bs[64][17];

    const int tid = threadIdx.x;
    const int tx = tid & 15, ty = tid >> 4;
    const int lr = tid >> 2, lk = (tid & 3) << 2;

    const int arow = rt * 64 + lr;
    const int tok  = (arow < cnt) ? g_slot[base + arow] : -1;
    const float* arowp = (tok >= 0) ? (x + (size_t)tok * DM) : nullptr;
    const float* browp = w1 + ((size_t)e * FFH + (size_t)(ct * 64 + lr)) * DM;

    float acc[4][4];
#pragma unroll
    for (int i = 0; i < 4; i++)
#pragma unroll
        for (int j = 0; j < 4; j++) acc[i][j] = 0.0f;

    for (int kt = 0; kt < DM; kt += 16) {
        float4 av = arowp ? *reinterpret_cast<const float4*>(arowp + kt + lk)
                          : make_float4(0.f, 0.f, 0.f, 0.f);
        float4 bv = *reinterpret_cast<const float4*>(browp + kt + lk);
        __syncthreads();
        As[lr][lk] = av.x; As[lr][lk + 1] = av.y; As[lr][lk + 2] = av.z; As[lr][lk + 3] = av.w;
        Bs[lr][lk] = bv.x; Bs[lr][lk + 1] = bv.y; Bs[lr][lk + 2] = bv.z; Bs[lr][lk + 3] = bv.w;
        __syncthreads();
#pragma unroll
        for (int kk = 0; kk < 16; kk++) {
            float a0 = As[ty * 4 + 0][kk], a1 = As[ty * 4 + 1][kk];
            float a2 = As[ty * 4 + 2][kk], a3 = As[ty * 4 + 3][kk];
            float b0 = Bs[tx * 4 + 0][kk], b1v = Bs[tx * 4 + 1][kk];
            float b2v = Bs[tx * 4 + 2][kk], b3 = Bs[tx * 4 + 3][kk];
            acc[0][0] = fmaf(a0, b0, acc[0][0]); acc[0][1] = fmaf(a0, b1v, acc[0][1]);
            acc[0][2] = fmaf(a0, b2v, acc[0][2]); acc[0][3] = fmaf(a0, b3, acc[0][3]);
            acc[1][0] = fmaf(a1, b0, acc[1][0]); acc[1][1] = fmaf(a1, b1v, acc[1][1]);
            acc[1][2] = fmaf(a1, b2v, acc[1][2]); acc[1][3] = fmaf(a1, b3, acc[1][3]);
            acc[2][0] = fmaf(a2, b0, acc[2][0]); acc[2][1] = fmaf(a2, b1v, acc[2][1]);
            acc[2][2] = fmaf(a2, b2v, acc[2][2]); acc[2][3] = fmaf(a2, b3, acc[2][3]);
            acc[3][0] = fmaf(a3, b0, acc[3][0]); acc[3][1] = fmaf(a3, b1v, acc[3][1]);
            acc[3][2] = fmaf(a3, b2v, acc[3][2]); acc[3][3] = fmaf(a3, b3, acc[3][3]);
        }
    }

#pragma unroll
    for (int i = 0; i < 4; i++) {
        int row = rt * 64 + ty * 4 + i;
        if (row >= cnt) continue;
#pragma unroll
        for (int j = 0; j < 4; j++) {
            int col = ct * 64 + tx * 4 + j;
            float v = acc[i][j] + b1[e * FFH + col];
            float s = v / (1.0f + expf(-v));   // silu
            g_hbuf[(size_t)(base + row) * FFH + col] = s;
        }
    }
}

// ---------------- GEMM2: out += cw * (h @ w2[e]^T + b2[e]) ----------------
__global__ void __launch_bounds__(256) gemm2_kernel(const float* __restrict__ w2,
                                                    const float* __restrict__ b2,
                                                    float* __restrict__ out) {
    const int e   = blockIdx.z;
    const int cnt = g_counts[e];
    const int rt  = blockIdx.x;
    if (rt * 64 >= cnt) return;
    const int base = g_aoff[e];
    const int ct   = blockIdx.y;

    __shared__ float As[64][17];
    __shared__ float Bs[64][17];

    const int tid = threadIdx.x;
    const int tx = tid & 15, ty = tid >> 4;
    const int lr = tid >> 2, lk = (tid & 3) << 2;

    const int arow = rt * 64 + lr;
    const bool aval = (arow < cnt);
    const float* arowp = aval ? (g_hbuf + (size_t)(base + arow) * FFH) : nullptr;
    const float* browp = w2 + ((size_t)e * DM + (size_t)(ct * 64 + lr)) * FFH;

    float acc[4][4];
#pragma unroll
    for (int i = 0; i < 4; i++)
#pragma unroll
        for (int j = 0; j < 4; j++) acc[i][j] = 0.0f;

    for (int kt = 0; kt < FFH; kt += 16) {
        float4 av = arowp ? *reinterpret_cast<const float4*>(arowp + kt + lk)
                          : make_float4(0.f, 0.f, 0.f, 0.f);
        float4 bv = *reinterpret_cast<const float4*>(browp + kt + lk);
        __syncthreads();
        As[lr][lk] = av.x; As[lr][lk + 1] = av.y; As[lr][lk + 2] = av.z; As[lr][lk + 3] = av.w;
        Bs[lr][lk] = bv.x; Bs[lr][lk + 1] = bv.y; Bs[lr][lk + 2] = bv.z; Bs[lr][lk + 3] = bv.w;
        __syncthreads();
#pragma unroll
        for (int kk = 0; kk < 16; kk++) {
            float a0 = As[ty * 4 + 0][kk], a1 = As[ty * 4 + 1][kk];
            float a2 = As[ty * 4 + 2][kk], a3 = As[ty * 4 + 3][kk];
            float b0 = Bs[tx * 4 + 0][kk], b1v = Bs[tx * 4 + 1][kk];
            float b2v = Bs[tx * 4 + 2][kk], b3 = Bs[tx * 4 + 3][kk];
            acc[0][0] = fmaf(a0, b0, acc[0][0]); acc[0][1] = fmaf(a0, b1v, acc[0][1]);
            acc[0][2] = fmaf(a0, b2v, acc[0][2]); acc[0][3] = fmaf(a0, b3, acc[0][3]);
            acc[1][0] = fmaf(a1, b0, acc[1][0]); acc[1][1] = fmaf(a1, b1v, acc[1][1]);
            acc[1][2] = fmaf(a1, b2v, acc[1][2]); acc[1][3] = fmaf(a1, b3, acc[1][3]);
            acc[2][0] = fmaf(a2, b0, acc[2][0]); acc[2][1] = fmaf(a2, b1v, acc[2][1]);
            acc[2][2] = fmaf(a2, b2v, acc[2][2]); acc[2][3] = fmaf(a2, b3, acc[2][3]);
            acc[3][0] = fmaf(a3, b0, acc[3][0]); acc[3][1] = fmaf(a3, b1v, acc[3][1]);
            acc[3][2] = fmaf(a3, b2v, acc[3][2]); acc[3][3] = fmaf(a3, b3, acc[3][3]);
        }
    }

#pragma unroll
    for (int i = 0; i < 4; i++) {
        int row = rt * 64 + ty * 4 + i;
        if (row >= cnt) continue;
        int tok  = g_slot[base + row];
        float cw = g_slotw[base + row];
#pragma unroll
        for (int j = 0; j < 4; j++) {
            int col = ct * 64 + tx * 4 + j;
            float v = acc[i][j] + b2[e * DM + col];
            atomicAdd(out + (size_t)tok * DM + col, cw * v);
        }
    }
}

// ---------------- launch ----------------
extern "C" void kernel_launch(void* const* d_in, const int* in_sizes, int n_in,
                              void* d_out, int out_size) {
    const float* x  = (const float*)d_in[0];
    const float* rw = (const float*)d_in[1];
    const float* w1 = (const float*)d_in[2];
    const float* b1 = (const float*)d_in[3];
    const float* w2 = (const float*)d_in[4];
    const float* b2 = (const float*)d_in[5];
    float* out = (float*)d_out;

    float* auxp = (out_size > N_TOK * DM) ? (out + (size_t)N_TOK * DM) : nullptr;

    init_kernel<<<256, 256>>>(out, out_size);
    router_kernel<<<(N_TOK + 7) / 8, 256>>>(x, rw);
    finalize_kernel<<<1, 32>>>(auxp);
    scatter_kernel<<<(N_TOK + 255) / 256, 256>>>();

    dim3 g1(64, FFH / 64, N_EXP);   // row tiles x H tiles x experts (idle tiles exit)
    gemm1_kernel<<<g1, 256>>>(x, w1, b1);

    dim3 g2(64, DM / 64, N_EXP);
    gemm2_kernel<<<g2, 256>>>(w2, b2, out);
}

// round 2
// speedup vs baseline: 3.3070x; 3.3070x over previous
#include <cuda_runtime.h>
#include <cuda_bf16.h>
#include <math.h>

#define N_TOK   4096
#define DM      1024
#define N_EXP   8
#define FFH     2048
#define ROWS_PAD 8704

// ---------------- device scratch ----------------
__device__ float g_hbuf[(size_t)ROWS_PAD * FFH];
__device__ int   g_slot[ROWS_PAD];
__device__ float g_slotw[ROWS_PAD];
__device__ int   g_counts[N_EXP];
__device__ float g_probsum[N_EXP];
__device__ int   g_aoff[N_EXP + 1];
__device__ int   g_cursor[N_EXP];
__device__ int   g_tok_e[N_TOK * 2];
__device__ float g_tok_w[N_TOK * 2];

// ---------------- init ----------------
__global__ void init_kernel(float* __restrict__ out, int out_elems) {
    int i = blockIdx.x * blockDim.x + threadIdx.x;
    int stride = gridDim.x * blockDim.x;
    for (int j = i; j < out_elems; j += stride) out[j] = 0.0f;
    if (blockIdx.x == 0 && threadIdx.x < N_EXP) {
        g_counts[threadIdx.x]  = 0;
        g_probsum[threadIdx.x] = 0.0f;
    }
}

// ---------------- router (warp/token) ----------------
__global__ void __launch_bounds__(256) router_kernel(const float* __restrict__ x,
                                                     const float* __restrict__ rw) {
    int warp = blockIdx.x * 8 + (threadIdx.x >> 5);
    int lane = threadIdx.x & 31;
    if (warp >= N_TOK) return;

    const float* xr = x + (size_t)warp * DM;
    float acc[N_EXP];
#pragma unroll
    for (int e = 0; e < N_EXP; e++) acc[e] = 0.0f;

    for (int j = lane; j < DM; j += 32) {
        float xv = xr[j];
#pragma unroll
        for (int e = 0; e < N_EXP; e++)
            acc[e] = fmaf(xv, rw[e * DM + j], acc[e]);
    }
#pragma unroll
    for (int e = 0; e < N_EXP; e++) {
#pragma unroll
        for (int o = 16; o > 0; o >>= 1)
            acc[e] += __shfl_xor_sync(0xFFFFFFFFu, acc[e], o);
    }

    if (lane == 0) {
        float m = acc[0];
#pragma unroll
        for (int e = 1; e < N_EXP; e++) m = fmaxf(m, acc[e]);
        float ex[N_EXP], s = 0.0f;
#pragma unroll
        for (int e = 0; e < N_EXP; e++) { ex[e] = expf(acc[e] - m); s += ex[e]; }
        float inv = 1.0f / s;

        int i0 = 0;
#pragma unroll
        for (int e = 1; e < N_EXP; e++) if (acc[e] > acc[i0]) i0 = e;
        int i1 = -1;
#pragma unroll
        for (int e = 0; e < N_EXP; e++) {
            if (e == i0) continue;
            if (i1 < 0 || acc[e] > acc[i1]) i1 = e;
        }
        float p0 = ex[i0] * inv, p1 = ex[i1] * inv;
        float rcp = 1.0f / (p0 + p1);
        g_tok_e[2 * warp + 0] = i0; g_tok_w[2 * warp + 0] = p0 * rcp;
        g_tok_e[2 * warp + 1] = i1; g_tok_w[2 * warp + 1] = p1 * rcp;

        atomicAdd(&g_counts[i0], 1);
        atomicAdd(&g_counts[i1], 1);
#pragma unroll
        for (int e = 0; e < N_EXP; e++)
            atomicAdd(&g_probsum[e], ex[e] * inv);
    }
}

// ---------------- finalize ----------------
__global__ void finalize_kernel(float* auxp) {
    if (threadIdx.x == 0 && blockIdx.x == 0) {
        int off = 0;
        float s = 0.0f;
        for (int e = 0; e < N_EXP; e++) {
            g_aoff[e] = off;
            off += (g_counts[e] + 63) & ~63;
            g_cursor[e] = 0;
            float f_i = (float)g_counts[e] / (float)(N_TOK * 2);
            float P_i = g_probsum[e] / (float)N_TOK;
            s += f_i * P_i;
        }
        g_aoff[N_EXP] = off;
        if (auxp) *auxp = (float)N_EXP * s;
    }
}

// ---------------- scatter ----------------
__global__ void scatter_kernel() {
    int t = blockIdx.x * blockDim.x + threadIdx.x;
    if (t >= N_TOK) return;
#pragma unroll
    for (int k = 0; k < 2; k++) {
        int e = g_tok_e[2 * t + k];
        int p = atomicAdd(&g_cursor[e], 1);
        int idx = g_aoff[e] + p;
        g_slot[idx]  = t;
        g_slotw[idx] = g_tok_w[2 * t + k];
    }
}

// ---------------- tf32 helpers ----------------
__device__ __forceinline__ unsigned f2tf(float f) {
    unsigned r;
    asm("cvt.rna.tf32.f32 %0, %1;" : "=r"(r) : "f"(f));
    return r;
}
__device__ __forceinline__ void mma_tf32(float* c, const unsigned* a, const unsigned* b) {
    asm volatile("mma.sync.aligned.m16n8k8.row.col.f32.tf32.tf32.f32 "
                 "{%0,%1,%2,%3}, {%4,%5,%6,%7}, {%8,%9}, {%0,%1,%2,%3};"
                 : "+f"(c[0]), "+f"(c[1]), "+f"(c[2]), "+f"(c[3])
                 : "r"(a[0]), "r"(a[1]), "r"(a[2]), "r"(a[3]),
                   "r"(b[0]), "r"(b[1]));
}

#define LDA 36   // smem row stride (floats): conflict-free (4g+c) bank map

// ---------------- GEMM1: h = silu(gather(x) @ w1[e]^T + b1[e]) ----------------
__global__ void __launch_bounds__(256, 2) gemm1_kernel(const float* __restrict__ x,
                                                       const float* __restrict__ w1,
                                                       const float* __restrict__ b1) {
    const int e   = blockIdx.z;
    const int cnt = g_counts[e];
    const int rt  = blockIdx.x;
    if (rt * 128 >= cnt) return;
    const int base = g_aoff[e];
    const int ct   = blockIdx.y;

    __shared__ float As[128 * LDA];
    __shared__ float Bs[128 * LDA];

    const int tid  = threadIdx.x;
    const int wid  = tid >> 5, lane = tid & 31;
    const int wm   = wid >> 1, wn = wid & 1;        // 4x2 warp grid
    const int g    = lane >> 2, c4l = lane & 3;

    const float* wB = w1 + ((size_t)e * FFH + (size_t)ct * 128) * DM;

    float acc[2][8][4];
#pragma unroll
    for (int mt = 0; mt < 2; mt++)
#pragma unroll
        for (int nt = 0; nt < 8; nt++)
#pragma unroll
            for (int q = 0; q < 4; q++) acc[mt][nt][q] = 0.0f;

    for (int ks = 0; ks < DM; ks += 32) {
        __syncthreads();
#pragma unroll
        for (int t = 0; t < 4; t++) {
            int i = tid + t * 256;          // 0..1023
            int row = i >> 3;
            int col = (i & 7) << 2;
            int grow = rt * 128 + row;
            float4 av = make_float4(0.f, 0.f, 0.f, 0.f);
            if (grow < cnt) {
                int tok = g_slot[base + grow];
                av = *reinterpret_cast<const float4*>(x + (size_t)tok * DM + ks + col);
            }
            float* ap = As + row * LDA + col;
            ap[0] = __uint_as_float(f2tf(av.x));
            ap[1] = __uint_as_float(f2tf(av.y));
            ap[2] = __uint_as_float(f2tf(av.z));
            ap[3] = __uint_as_float(f2tf(av.w));

            float4 bv = *reinterpret_cast<const float4*>(wB + (size_t)row * DM + ks + col);
            float* bp = Bs + row * LDA + col;
            bp[0] = __uint_as_float(f2tf(bv.x));
            bp[1] = __uint_as_float(f2tf(bv.y));
            bp[2] = __uint_as_float(f2tf(bv.z));
            bp[3] = __uint_as_float(f2tf(bv.w));
        }
        __syncthreads();

#pragma unroll
        for (int kt = 0; kt < 4; kt++) {
            const int kb = kt * 8;
            unsigned a[2][4], b[8][2];
#pragma unroll
            for (int mt = 0; mt < 2; mt++) {
                int r = wm * 32 + mt * 16 + g;
                a[mt][0] = __float_as_uint(As[r * LDA + kb + c4l]);
                a[mt][1] = __float_as_uint(As[(r + 8) * LDA + kb + c4l]);
                a[mt][2] = __float_as_uint(As[r * LDA + kb + c4l + 4]);
                a[mt][3] = __float_as_uint(As[(r + 8) * LDA + kb + c4l + 4]);
            }
#pragma unroll
            for (int nt = 0; nt < 8; nt++) {
                int n = wn * 64 + nt * 8 + g;
                b[nt][0] = __float_as_uint(Bs[n * LDA + kb + c4l]);
                b[nt][1] = __float_as_uint(Bs[n * LDA + kb + c4l + 4]);
            }
#pragma unroll
            for (int mt = 0; mt < 2; mt++)
#pragma unroll
                for (int nt = 0; nt < 8; nt++)
                    mma_tf32(acc[mt][nt], a[mt], b[nt]);
        }
    }

    // epilogue: bias + silu -> g_hbuf
#pragma unroll
    for (int mt = 0; mt < 2; mt++) {
#pragma unroll
        for (int half = 0; half < 2; half++) {
            int r = rt * 128 + wm * 32 + mt * 16 + half * 8 + g;
            if (r >= cnt) continue;
            size_t hrow = (size_t)(base + r) * FFH;
#pragma unroll
            for (int nt = 0; nt < 8; nt++) {
                int col = ct * 128 + wn * 64 + nt * 8 + 2 * c4l;
                float v0 = acc[mt][nt][half * 2 + 0] + b1[e * FFH + col];
                float v1 = acc[mt][nt][half * 2 + 1] + b1[e * FFH + col + 1];
                g_hbuf[hrow + col]     = v0 / (1.0f + expf(-v0));
                g_hbuf[hrow + col + 1] = v1 / (1.0f + expf(-v1));
            }
        }
    }
}

// ---------------- GEMM2: out += cw * (h @ w2[e]^T + b2[e]) ----------------
__global__ void __launch_bounds__(256, 2) gemm2_kernel(const float* __restrict__ w2,
                                                       const float* __restrict__ b2,
                                                       float* __restrict__ out) {
    const int e   = blockIdx.z;
    const int cnt = g_counts[e];
    const int rt  = blockIdx.x;
    if (rt * 128 >= cnt) return;
    const int base = g_aoff[e];
    const int ct   = blockIdx.y;

    __shared__ float As[128 * LDA];
    __shared__ float Bs[128 * LDA];

    const int tid  = threadIdx.x;
    const int wid  = tid >> 5, lane = tid & 31;
    const int wm   = wid >> 1, wn = wid & 1;
    const int g    = lane >> 2, c4l = lane & 3;

    const float* wB = w2 + ((size_t)e * DM + (size_t)ct * 128) * FFH;

    float acc[2][8][4];
#pragma unroll
    for (int mt = 0; mt < 2; mt++)
#pragma unroll
        for (int nt = 0; nt < 8; nt++)
#pragma unroll
            for (int q = 0; q < 4; q++) acc[mt][nt][q] = 0.0f;

    for (int ks = 0; ks < FFH; ks += 32) {
        __syncthreads();
#pragma unroll
        for (int t = 0; t < 4; t++) {
            int i = tid + t * 256;
            int row = i >> 3;
            int col = (i & 7) << 2;
            int grow = rt * 128 + row;
            float4 av = make_float4(0.f, 0.f, 0.f, 0.f);
            if (grow < cnt) {
                av = *reinterpret_cast<const float4*>(g_hbuf + (size_t)(base + grow) * FFH + ks + col);
            }
            float* ap = As + row * LDA + col;
            ap[0] = __uint_as_float(f2tf(av.x));
            ap[1] = __uint_as_float(f2tf(av.y));
            ap[2] = __uint_as_float(f2tf(av.z));
            ap[3] = __uint_as_float(f2tf(av.w));

            float4 bv = *reinterpret_cast<const float4*>(wB + (size_t)row * FFH + ks + col);
            float* bp = Bs + row * LDA + col;
            bp[0] = __uint_as_float(f2tf(bv.x));
            bp[1] = __uint_as_float(f2tf(bv.y));
            bp[2] = __uint_as_float(f2tf(bv.z));
            bp[3] = __uint_as_float(f2tf(bv.w));
        }
        __syncthreads();

#pragma unroll
        for (int kt = 0; kt < 4; kt++) {
            const int kb = kt * 8;
            unsigned a[2][4], b[8][2];
#pragma unroll
            for (int mt = 0; mt < 2; mt++) {
                int r = wm * 32 + mt * 16 + g;
                a[mt][0] = __float_as_uint(As[r * LDA + kb + c4l]);
                a[mt][1] = __float_as_uint(As[(r + 8) * LDA + kb + c4l]);
                a[mt][2] = __float_as_uint(As[r * LDA + kb + c4l + 4]);
                a[mt][3] = __float_as_uint(As[(r + 8) * LDA + kb + c4l + 4]);
            }
#pragma unroll
            for (int nt = 0; nt < 8; nt++) {
                int n = wn * 64 + nt * 8 + g;
                b[nt][0] = __float_as_uint(Bs[n * LDA + kb + c4l]);
                b[nt][1] = __float_as_uint(Bs[n * LDA + kb + c4l + 4]);
            }
#pragma unroll
            for (int mt = 0; mt < 2; mt++)
#pragma unroll
                for (int nt = 0; nt < 8; nt++)
                    mma_tf32(acc[mt][nt], a[mt], b[nt]);
        }
    }

    // epilogue: bias + weighted atomic combine
#pragma unroll
    for (int mt = 0; mt < 2; mt++) {
#pragma unroll
        for (int half = 0; half < 2; half++) {
            int r = rt * 128 + wm * 32 + mt * 16 + half * 8 + g;
            if (r >= cnt) continue;
            int tok  = g_slot[base + r];
            float cw = g_slotw[base + r];
            float* orow = out + (size_t)tok * DM;
#pragma unroll
            for (int nt = 0; nt < 8; nt++) {
                int col = ct * 128 + wn * 64 + nt * 8 + 2 * c4l;
                float v0 = acc[mt][nt][half * 2 + 0] + b2[e * DM + col];
                float v1 = acc[mt][nt][half * 2 + 1] + b2[e * DM + col + 1];
                atomicAdd(orow + col,     cw * v0);
                atomicAdd(orow + col + 1, cw * v1);
            }
        }
    }
}

// ---------------- launch ----------------
extern "C" void kernel_launch(void* const* d_in, const int* in_sizes, int n_in,
                              void* d_out, int out_size) {
    const float* x  = (const float*)d_in[0];
    const float* rw = (const float*)d_in[1];
    const float* w1 = (const float*)d_in[2];
    const float* b1 = (const float*)d_in[3];
    const float* w2 = (const float*)d_in[4];
    const float* b2 = (const float*)d_in[5];
    float* out = (float*)d_out;

    float* auxp = (out_size > N_TOK * DM) ? (out + (size_t)N_TOK * DM) : nullptr;

    init_kernel<<<256, 256>>>(out, out_size);
    router_kernel<<<(N_TOK + 7) / 8, 256>>>(x, rw);
    finalize_kernel<<<1, 32>>>(auxp);
    scatter_kernel<<<(N_TOK + 255) / 256, 256>>>();

    dim3 g1(64, FFH / 128, N_EXP);   // worst-case row tiles; idle tiles exit
    gemm1_kernel<<<g1, 256>>>(x, w1, b1);

    dim3 g2(64, DM / 128, N_EXP);
    gemm2_kernel<<<g2, 256>>>(w2, b2, out);
}